// round 14
// baseline (speedup 1.0000x reference)
#include <cuda_runtime.h>
#include <cuda_fp16.h>
#include <cstdint>

#define HDIM     128
#define INDIM    13
#define B_TOTAL  262144
#define TILE_M   64
#define NBT      (B_TOTAL / TILE_M)     // 4096
#define NTHREADS 256

// packed weights fp16: storage col = nh*256 + wn*64 + gate*16 + p,
// position p = 8b + 2q + e carries OUTPUT column j = 4q + 2b + e
__device__ __align__(16) __half g_W[512 * 144];
__device__ float  g_bias[512];

struct WP { const float *Wx[4], *bx[4], *Wh[4], *bh[4]; };

__global__ void prep_kernel(WP p) {
    int idx = blockIdx.x * blockDim.x + threadIdx.x;
    if (idx < 512) {
        int r = idx & 255, nh = idx >> 8;
        int wn = r >> 6, gate = (r >> 4) & 3, pp = r & 15;
        int jl = 4 * ((pp >> 1) & 3) + 2 * (pp >> 3) + (pp & 1);
        int j = nh * 64 + wn * 16 + jl;
        g_bias[idx] = p.bx[gate][j] + p.bh[gate][j];
    }
    if (idx < 512 * 144) {
        int col = idx / 144, k = idx - col * 144;
        int r = col & 255, nh = col >> 8;
        int wn = r >> 6, gate = (r >> 4) & 3, pp = r & 15;
        int jl = 4 * ((pp >> 1) & 3) + 2 * (pp >> 3) + (pp & 1);
        int j = nh * 64 + wn * 16 + jl;
        float v = 0.f;
        if (k < INDIM)               v = p.Wx[gate][j * INDIM + k];
        else if (k >= 16 && k < 144) v = p.Wh[gate][j * HDIM + (k - 16)];
        g_W[col * 144 + k] = __float2half_rn(v);
    }
}

__device__ __forceinline__ uint32_t smem_u32(const void* p) {
    uint32_t a;
    asm("{ .reg .u64 t; cvta.to.shared.u64 t, %1; cvt.u32.u64 %0, t; }" : "=r"(a) : "l"(p));
    return a;
}
__device__ __forceinline__ void ldmx4(uint32_t& r0, uint32_t& r1, uint32_t& r2, uint32_t& r3,
                                      uint32_t addr) {
    asm volatile("ldmatrix.sync.aligned.m8n8.x4.shared.b16 {%0,%1,%2,%3}, [%4];"
                 : "=r"(r0), "=r"(r1), "=r"(r2), "=r"(r3) : "r"(addr));
}
__device__ __forceinline__ float fsig(float x) {
    float t;
    asm("tanh.approx.f32 %0, %1;" : "=f"(t) : "f"(x * 0.5f));
    return fmaf(t, 0.5f, 0.5f);
}
__device__ __forceinline__ float htanh(float x) { return fminf(fmaxf(x, -1.f), 1.f); }

// smem per CTA (total 114688 = 14 x 8KB exactly):
//   Bs 256x152 fp16 = 77824 | As 2 x (64x136 fp16 = 17408) | Xs 64x16 fp16 = 2048
#define SM_B    0u
#define SM_AS   77824u
#define SM_XS   112640u
#define SMEM_BYTES 114688u
#define APITCH  136
#define BPITCH  152
#define XPITCH  16
#define ABUF_B  17408u        // bytes per A buffer
#define ABUF_H  8704          // halves per A buffer

__global__ void __launch_bounds__(NTHREADS, 2)
lstm_kernel(const float* __restrict__ x_in, const float* __restrict__ h_in,
            const float* __restrict__ c_in, float* __restrict__ out)
{
    extern __shared__ char sm[];
    __half* Bs = (__half*)(sm + SM_B);
    __half* As = (__half*)(sm + SM_AS);    // two buffers back-to-back
    __half* Xs = (__half*)(sm + SM_XS);

    const int tid  = threadIdx.x;
    const int lane = tid & 31;
    const int wid  = tid >> 5;           // 0..7
    const int q    = lane & 3;
    const int gid  = lane >> 2;
    const int wm   = wid >> 2;           // 0..1 (rows wm*32..)
    const int wn   = wid & 3;            // 0..3 (cols wn*64..)

    const int nh     = blockIdx.x & 1;
    const int cidx   = blockIdx.x >> 1;
    const int npairs = gridDim.x >> 1;

    // stage weight half once: src 18 uint4/row -> dst 19 uint4/row (BPITCH 152)
    {
        const uint4* wsrc = (const uint4*)g_W + nh * 4608;
        uint4* wdst = (uint4*)Bs;
        #pragma unroll
        for (int it = 0; it < 18; it++) {
            int i = tid + it * NTHREADS;
            int r = i / 18, j = i - r * 18;
            wdst[r * 19 + j] = wsrc[i];
        }
    }
    if (tid < 128) ((uint4*)Xs)[tid] = make_uint4(0, 0, 0, 0);
    __syncthreads();   // zero-fill visible before prologue x writes

    const uint32_t adA0 = smem_u32(As) +
        (uint32_t)(((wm * 32 + (lane & 15)) * APITCH + (lane >> 4) * 8) * 2);
    const uint32_t adX = smem_u32(Xs) +
        (uint32_t)(((wm * 32 + (lane & 15)) * XPITCH + (lane >> 4) * 8) * 2);
    const uint32_t adB = smem_u32(Bs) +
        (uint32_t)(((wn * 64 + (lane >> 4) * 8 + (lane & 7)) * BPITCH
                    + ((lane >> 3) & 1) * 8) * 2);

    float binit[8][2];
    #pragma unroll
    for (int nt = 0; nt < 8; nt++) {
        binit[nt][0] = g_bias[nh * 256 + wn * 64 + nt * 8 + 2 * q + 0];
        binit[nt][1] = g_bias[nh * 256 + wn * 64 + nt * 8 + 2 * q + 1];
    }

    float* out_h  = out;
    float* out_h2 = out + (size_t)B_TOTAL * HDIM;
    float* out_c  = out + (size_t)2 * B_TOTAL * HDIM;

    const int colbase4 = nh * 64 + wn * 16 + 4 * q;

    // ---- prologue: tile(cidx) h -> As[0], x -> Xs ----
    {
        const int rb0 = cidx * TILE_M;
        #pragma unroll
        for (int it = 0; it < 4; it++) {
            int i = tid + it * NTHREADS;
            int r = i >> 4, c8 = (i & 15) * 8;
            const float4* hp = (const float4*)(h_in + (size_t)(rb0 + r) * HDIM + c8);
            float4 v0 = hp[0], v1 = hp[1];
            __half2 a0 = __floats2half2_rn(v0.x, v0.y);
            __half2 a1 = __floats2half2_rn(v0.z, v0.w);
            __half2 a2 = __floats2half2_rn(v1.x, v1.y);
            __half2 a3 = __floats2half2_rn(v1.z, v1.w);
            *(uint4*)(As + r * APITCH + c8) = make_uint4(
                *(uint32_t*)&a0, *(uint32_t*)&a1, *(uint32_t*)&a2, *(uint32_t*)&a3);
        }
        if (tid < 208) {
            float4 xv = ((const float4*)(x_in + (size_t)rb0 * INDIM))[tid];
            float xs4[4] = {xv.x, xv.y, xv.z, xv.w};
            #pragma unroll
            for (int u = 0; u < 4; u++) {
                int f = tid * 4 + u;
                int r = f / 13, c = f - r * 13;
                Xs[r * XPITCH + c] = __float2half_rn(xs4[u]);
            }
        }
    }
    __syncthreads();

    int p = 0;
    for (int bt = cidx; bt < NBT; bt += npairs) {
        const int rowbase = bt * TILE_M;
        int btn = bt + npairs; if (btn >= NBT) btn = bt;   // clamp: re-read, harmless
        const int rbn = btn * TILE_M;

        // ---- c preload (current tile)
        float4 cv[2][2];
        #pragma unroll
        for (int mt = 0; mt < 2; mt++)
            #pragma unroll
            for (int rs = 0; rs < 2; rs++) {
                int row = wm * 32 + mt * 16 + gid + 8 * rs;
                cv[mt][rs] = *(const float4*)(
                    c_in + (size_t)(rowbase + row) * HDIM + colbase4);
            }

        // ---- load NEXT tile h -> As[p^1] (acc regs dead here; no barrier after)
        {
            __half* Ad = As + (p ^ 1) * ABUF_H;
            #pragma unroll
            for (int it = 0; it < 4; it++) {
                int i = tid + it * NTHREADS;
                int r = i >> 4, c8 = (i & 15) * 8;
                const float4* hp = (const float4*)(h_in + (size_t)(rbn + r) * HDIM + c8);
                float4 v0 = hp[0], v1 = hp[1];
                __half2 a0 = __floats2half2_rn(v0.x, v0.y);
                __half2 a1 = __floats2half2_rn(v0.z, v0.w);
                __half2 a2 = __floats2half2_rn(v1.x, v1.y);
                __half2 a3 = __floats2half2_rn(v1.z, v1.w);
                *(uint4*)(Ad + r * APITCH + c8) = make_uint4(
                    *(uint32_t*)&a0, *(uint32_t*)&a1, *(uint32_t*)&a2, *(uint32_t*)&a3);
            }
        }
        // ---- x(next) into 4 regs, published at iteration end
        float4 xr = make_float4(0.f, 0.f, 0.f, 0.f);
        if (tid < 208) xr = ((const float4*)(x_in + (size_t)rbn * INDIM))[tid];

        // ---- MMA: ks0 from Xs, ks1..8 from As[p]
        const uint32_t adAp = adA0 + (uint32_t)p * ABUF_B;
        float acc[2][8][4];
        #pragma unroll
        for (int mt = 0; mt < 2; mt++)
            #pragma unroll
            for (int nt = 0; nt < 8; nt++) {
                acc[mt][nt][0] = binit[nt][0]; acc[mt][nt][1] = binit[nt][1];
                acc[mt][nt][2] = binit[nt][0]; acc[mt][nt][3] = binit[nt][1];
            }
        {
            uint32_t af[2][4], bf[8][2];
            ldmx4(af[0][0], af[0][1], af[0][2], af[0][3], adX);
            ldmx4(af[1][0], af[1][1], af[1][2], af[1][3], adX + 16 * XPITCH * 2);
            #pragma unroll
            for (int pb = 0; pb < 4; pb++)
                ldmx4(bf[2*pb][0], bf[2*pb][1], bf[2*pb+1][0], bf[2*pb+1][1],
                      adB + pb * (16 * BPITCH * 2));
            #pragma unroll
            for (int nt = 0; nt < 8; nt++)
                #pragma unroll
                for (int mt = 0; mt < 2; mt++)
                    asm("mma.sync.aligned.m16n8k16.row.col.f32.f16.f16.f32 "
                        "{%0,%1,%2,%3}, {%4,%5,%6,%7}, {%8,%9}, {%0,%1,%2,%3};"
                        : "+f"(acc[mt][nt][0]), "+f"(acc[mt][nt][1]),
                          "+f"(acc[mt][nt][2]), "+f"(acc[mt][nt][3])
                        : "r"(af[mt][0]), "r"(af[mt][1]), "r"(af[mt][2]), "r"(af[mt][3]),
                          "r"(bf[nt][0]), "r"(bf[nt][1]));
        }
        #pragma unroll 1
        for (int ks = 1; ks < 9; ks++) {
            uint32_t af[2][4], bf[8][2];
            uint32_t a0 = adAp + (uint32_t)(ks - 1) * 32;
            ldmx4(af[0][0], af[0][1], af[0][2], af[0][3], a0);
            ldmx4(af[1][0], af[1][1], af[1][2], af[1][3], a0 + 16 * APITCH * 2);
            uint32_t b0a = adB + (uint32_t)ks * 32;
            #pragma unroll
            for (int pb = 0; pb < 4; pb++)
                ldmx4(bf[2*pb][0], bf[2*pb][1], bf[2*pb+1][0], bf[2*pb+1][1],
                      b0a + pb * (16 * BPITCH * 2));
            #pragma unroll
            for (int nt = 0; nt < 8; nt++)
                #pragma unroll
                for (int mt = 0; mt < 2; mt++)
                    asm("mma.sync.aligned.m16n8k16.row.col.f32.f16.f16.f32 "
                        "{%0,%1,%2,%3}, {%4,%5,%6,%7}, {%8,%9}, {%0,%1,%2,%3};"
                        : "+f"(acc[mt][nt][0]), "+f"(acc[mt][nt][1]),
                          "+f"(acc[mt][nt][2]), "+f"(acc[mt][nt][3])
                        : "r"(af[mt][0]), "r"(af[mt][1]), "r"(af[mt][2]), "r"(af[mt][3]),
                          "r"(bf[nt][0]), "r"(bf[nt][1]));
        }

        // ---- epilogue + direct STG.128
        #pragma unroll
        for (int mt = 0; mt < 2; mt++) {
            #pragma unroll
            for (int rs = 0; rs < 2; rs++) {
                const int row = wm * 32 + mt * 16 + gid + 8 * rs;
                float4 cc = cv[mt][rs];
                float cin[4] = {cc.x, cc.y, cc.z, cc.w};
                float hv[4], cw[4];
                #pragma unroll
                for (int b = 0; b < 2; b++)
                    #pragma unroll
                    for (int e = 0; e < 2; e++) {
                        const int s = 2 * b + e, ci = rs * 2 + e;
                        float it = fsig(acc[mt][0 + b][ci]);
                        float ft = fsig(acc[mt][2 + b][ci]);
                        float gt = htanh(acc[mt][4 + b][ci]);
                        float ot = fsig(acc[mt][6 + b][ci]);
                        float ct = ft * cin[s] + it * gt;
                        hv[s] = ot * htanh(ct); cw[s] = ct;
                    }
                float4 hq = make_float4(hv[0], hv[1], hv[2], hv[3]);
                float4 cq = make_float4(cw[0], cw[1], cw[2], cw[3]);
                size_t o = (size_t)(rowbase + row) * HDIM + colbase4;
                *(float4*)(out_h + o)  = hq;
                *(float4*)(out_h2 + o) = hq;
                *(float4*)(out_c + o)  = cq;
            }
        }

        __syncthreads();   // bar1: MMA reads of Xs/As[p] done; As[p^1] writes done
        // ---- publish x(t+1) into Xs
        if (tid < 208) {
            float xs4[4] = {xr.x, xr.y, xr.z, xr.w};
            #pragma unroll
            for (int u = 0; u < 4; u++) {
                int f = tid * 4 + u;
                int r = f / 13, c = f - r * 13;
                Xs[r * XPITCH + c] = __float2half_rn(xs4[u]);
            }
        }
        __syncthreads();   // bar2: Xs(t+1) published
        p ^= 1;
    }
}

extern "C" void kernel_launch(void* const* d_in, const int* in_sizes, int n_in,
                              void* d_out, int out_size) {
    WP p;
    for (int g = 0; g < 4; g++) {
        p.Wx[g] = (const float*)d_in[3 + 4 * g];
        p.bx[g] = (const float*)d_in[4 + 4 * g];
        p.Wh[g] = (const float*)d_in[5 + 4 * g];
        p.bh[g] = (const float*)d_in[6 + 4 * g];
    }
    prep_kernel<<<(512 * 144 + 255) / 256, 256>>>(p);

    int dev = 0, sms = 0;
    cudaGetDevice(&dev);
    cudaDeviceGetAttribute(&sms, cudaDevAttrMultiProcessorCount, dev);
    if (sms <= 0) sms = 152;
    int grid = sms * 2;
    cudaFuncSetAttribute(lstm_kernel, cudaFuncAttributeMaxDynamicSharedMemorySize, SMEM_BYTES);
    lstm_kernel<<<grid, NTHREADS, SMEM_BYTES>>>(
        (const float*)d_in[0], (const float*)d_in[1], (const float*)d_in[2], (float*)d_out);
}

// round 15
// speedup vs baseline: 1.7185x; 1.7185x over previous
#include <cuda_runtime.h>
#include <cuda_fp16.h>
#include <cstdint>

#define HDIM     128
#define INDIM    13
#define B_TOTAL  262144
#define TILE_M   64
#define NBT      (B_TOTAL / TILE_M)     // 4096
#define NTHREADS 256

// packed weights fp16: storage col = nh*256 + wn*64 + gate*16 + p,
// position p = 8b + 2q + e carries OUTPUT column j = 4q + 2b + e
__device__ __align__(16) __half g_W[512 * 144];
__device__ float  g_bias[512];

struct WP { const float *Wx[4], *bx[4], *Wh[4], *bh[4]; };

__global__ void prep_kernel(WP p) {
    int idx = blockIdx.x * blockDim.x + threadIdx.x;
    if (idx < 512) {
        int r = idx & 255, nh = idx >> 8;
        int wn = r >> 6, gate = (r >> 4) & 3, pp = r & 15;
        int jl = 4 * ((pp >> 1) & 3) + 2 * (pp >> 3) + (pp & 1);
        int j = nh * 64 + wn * 16 + jl;
        g_bias[idx] = p.bx[gate][j] + p.bh[gate][j];
    }
    if (idx < 512 * 144) {
        int col = idx / 144, k = idx - col * 144;
        int r = col & 255, nh = col >> 8;
        int wn = r >> 6, gate = (r >> 4) & 3, pp = r & 15;
        int jl = 4 * ((pp >> 1) & 3) + 2 * (pp >> 3) + (pp & 1);
        int j = nh * 64 + wn * 16 + jl;
        float v = 0.f;
        if (k < INDIM)               v = p.Wx[gate][j * INDIM + k];
        else if (k >= 16 && k < 144) v = p.Wh[gate][j * HDIM + (k - 16)];
        g_W[col * 144 + k] = __float2half_rn(v);
    }
}

__device__ __forceinline__ uint32_t smem_u32(const void* p) {
    uint32_t a;
    asm("{ .reg .u64 t; cvta.to.shared.u64 t, %1; cvt.u32.u64 %0, t; }" : "=r"(a) : "l"(p));
    return a;
}
__device__ __forceinline__ void ldmx4(uint32_t& r0, uint32_t& r1, uint32_t& r2, uint32_t& r3,
                                      uint32_t addr) {
    asm volatile("ldmatrix.sync.aligned.m8n8.x4.shared.b16 {%0,%1,%2,%3}, [%4];"
                 : "=r"(r0), "=r"(r1), "=r"(r2), "=r"(r3) : "r"(addr));
}
__device__ __forceinline__ float fsig(float x) {
    float t;
    asm("tanh.approx.f32 %0, %1;" : "=f"(t) : "f"(x * 0.5f));
    return fmaf(t, 0.5f, 0.5f);
}
__device__ __forceinline__ float htanh(float x) { return fminf(fmaxf(x, -1.f), 1.f); }

// smem per CTA: Bs 256x152 fp16 = 77824 | As 64x136 fp16 = 17408 | Xs 64x24 fp16 = 3072
#define SM_B    0u
#define SM_AS   77824u
#define SM_XS   95232u
#define SMEM_BYTES 98304u
#define APITCH  136
#define BPITCH  152
#define XPITCH  24

__global__ void __launch_bounds__(NTHREADS, 2)
lstm_kernel(const float* __restrict__ x_in, const float* __restrict__ h_in,
            const float* __restrict__ c_in, float* __restrict__ out)
{
    extern __shared__ char sm[];
    __half* Bs = (__half*)(sm + SM_B);
    __half* As = (__half*)(sm + SM_AS);
    __half* Xs = (__half*)(sm + SM_XS);

    const int tid  = threadIdx.x;
    const int lane = tid & 31;
    const int wid  = tid >> 5;           // 0..7
    const int q    = lane & 3;
    const int gid  = lane >> 2;
    const int wm   = wid >> 2;           // 0..1 (rows wm*32..)
    const int wn   = wid & 3;            // 0..3 (cols wn*64..)

    const int nh     = blockIdx.x & 1;
    const int cidx   = blockIdx.x >> 1;
    const int npairs = gridDim.x >> 1;

    // stage weight half once: src 18 uint4/row -> dst 19 uint4/row
    {
        const uint4* wsrc = (const uint4*)g_W + nh * 4608;
        uint4* wdst = (uint4*)Bs;
        #pragma unroll
        for (int it = 0; it < 18; it++) {
            int i = tid + it * NTHREADS;
            int r = i / 18, j = i - r * 18;
            wdst[r * 19 + j] = wsrc[i];
        }
    }
    if (tid < 192) ((uint4*)Xs)[tid] = make_uint4(0, 0, 0, 0);
    __syncthreads();   // zero-fill & weights visible before first tile loads

    // one-time phase stagger: desync the two co-resident CTAs (nh pair) by ~half a tile
    if (nh == 1) {
        long long t0 = clock64();
        while (clock64() - t0 < 6000) { }
    }

    const uint32_t adA = smem_u32(As) +
        (uint32_t)(((wm * 32 + (lane & 15)) * APITCH + (lane >> 4) * 8) * 2);
    const uint32_t adX = smem_u32(Xs) +
        (uint32_t)(((wm * 32 + (lane & 15)) * XPITCH + (lane >> 4) * 8) * 2);
    const uint32_t adB = smem_u32(Bs) +
        (uint32_t)(((wn * 64 + (lane >> 4) * 8 + (lane & 7)) * BPITCH
                    + ((lane >> 3) & 1) * 8) * 2);

    float binit[8][2];
    #pragma unroll
    for (int nt = 0; nt < 8; nt++) {
        binit[nt][0] = g_bias[nh * 256 + wn * 64 + nt * 8 + 2 * q + 0];
        binit[nt][1] = g_bias[nh * 256 + wn * 64 + nt * 8 + 2 * q + 1];
    }

    // loop-invariant x scatter indices (f = tid*4 + u -> row, col)
    int xrow[4], xcol[4];
    #pragma unroll
    for (int u = 0; u < 4; u++) {
        int f = tid * 4 + u;
        xrow[u] = f / 13;
        xcol[u] = f - xrow[u] * 13;
    }

    float* out_h  = out;
    float* out_h2 = out + (size_t)B_TOTAL * HDIM;
    float* out_c  = out + (size_t)2 * B_TOTAL * HDIM;

    const int colbase4 = nh * 64 + wn * 16 + 4 * q;

    for (int bt = cidx; bt < NBT; bt += npairs) {
        const int rowbase = bt * TILE_M;

        __syncthreads();   // all warps done reading As/Xs of previous tile

        // ---- c preload: LDG.128 (consumed at epilogue; latency hidden by MMA)
        float4 cv[2][2];
        #pragma unroll
        for (int mt = 0; mt < 2; mt++)
            #pragma unroll
            for (int rs = 0; rs < 2; rs++) {
                int row = wm * 32 + mt * 16 + gid + 8 * rs;
                cv[mt][rs] = *(const float4*)(
                    c_in + (size_t)(rowbase + row) * HDIM + colbase4);
            }

        // ---- h: LDG 2x float4 -> fp16 -> STS.128
        #pragma unroll
        for (int it = 0; it < 4; it++) {
            int i = tid + it * NTHREADS;
            int r = i >> 4, c8 = (i & 15) * 8;
            const float4* hp = (const float4*)(h_in + (size_t)(rowbase + r) * HDIM + c8);
            float4 v0 = hp[0], v1 = hp[1];
            __half2 a0 = __floats2half2_rn(v0.x, v0.y);
            __half2 a1 = __floats2half2_rn(v0.z, v0.w);
            __half2 a2 = __floats2half2_rn(v1.x, v1.y);
            __half2 a3 = __floats2half2_rn(v1.z, v1.w);
            *(uint4*)(As + r * APITCH + c8) = make_uint4(
                *(uint32_t*)&a0, *(uint32_t*)&a1, *(uint32_t*)&a2, *(uint32_t*)&a3);
        }
        // ---- x: flat contiguous LDG.128, scatter-convert
        if (tid < 208) {
            float4 xv = ((const float4*)(x_in + (size_t)rowbase * INDIM))[tid];
            float xs4[4] = {xv.x, xv.y, xv.z, xv.w};
            #pragma unroll
            for (int u = 0; u < 4; u++)
                Xs[xrow[u] * XPITCH + xcol[u]] = __float2half_rn(xs4[u]);
        }
        __syncthreads();   // As/Xs ready

        // ---- MMA: warp tile 32x64, K = 144 (ks0 from Xs, ks1..8 from As)
        float acc[2][8][4];
        #pragma unroll
        for (int mt = 0; mt < 2; mt++)
            #pragma unroll
            for (int nt = 0; nt < 8; nt++) {
                acc[mt][nt][0] = binit[nt][0]; acc[mt][nt][1] = binit[nt][1];
                acc[mt][nt][2] = binit[nt][0]; acc[mt][nt][3] = binit[nt][1];
            }
        {
            uint32_t af[2][4], bf[8][2];
            ldmx4(af[0][0], af[0][1], af[0][2], af[0][3], adX);
            ldmx4(af[1][0], af[1][1], af[1][2], af[1][3], adX + 16 * XPITCH * 2);
            #pragma unroll
            for (int p = 0; p < 4; p++)
                ldmx4(bf[2*p][0], bf[2*p][1], bf[2*p+1][0], bf[2*p+1][1],
                      adB + p * (16 * BPITCH * 2));
            #pragma unroll
            for (int nt = 0; nt < 8; nt++)
                #pragma unroll
                for (int mt = 0; mt < 2; mt++)
                    asm("mma.sync.aligned.m16n8k16.row.col.f32.f16.f16.f32 "
                        "{%0,%1,%2,%3}, {%4,%5,%6,%7}, {%8,%9}, {%0,%1,%2,%3};"
                        : "+f"(acc[mt][nt][0]), "+f"(acc[mt][nt][1]),
                          "+f"(acc[mt][nt][2]), "+f"(acc[mt][nt][3])
                        : "r"(af[mt][0]), "r"(af[mt][1]), "r"(af[mt][2]), "r"(af[mt][3]),
                          "r"(bf[nt][0]), "r"(bf[nt][1]));
        }
        #pragma unroll 3
        for (int ks = 1; ks < 9; ks++) {
            uint32_t af[2][4], bf[8][2];
            uint32_t a0 = adA + (uint32_t)(ks - 1) * 32;
            ldmx4(af[0][0], af[0][1], af[0][2], af[0][3], a0);
            ldmx4(af[1][0], af[1][1], af[1][2], af[1][3], a0 + 16 * APITCH * 2);
            uint32_t b0a = adB + (uint32_t)ks * 32;
            #pragma unroll
            for (int p = 0; p < 4; p++)
                ldmx4(bf[2*p][0], bf[2*p][1], bf[2*p+1][0], bf[2*p+1][1],
                      b0a + p * (16 * BPITCH * 2));
            #pragma unroll
            for (int nt = 0; nt < 8; nt++)
                #pragma unroll
                for (int mt = 0; mt < 2; mt++)
                    asm("mma.sync.aligned.m16n8k16.row.col.f32.f16.f16.f32 "
                        "{%0,%1,%2,%3}, {%4,%5,%6,%7}, {%8,%9}, {%0,%1,%2,%3};"
                        : "+f"(acc[mt][nt][0]), "+f"(acc[mt][nt][1]),
                          "+f"(acc[mt][nt][2]), "+f"(acc[mt][nt][3])
                        : "r"(af[mt][0]), "r"(af[mt][1]), "r"(af[mt][2]), "r"(af[mt][3]),
                          "r"(bf[nt][0]), "r"(bf[nt][1]));
        }

        // ---- epilogue: 4 consecutive output cols per thread -> STG.128
        #pragma unroll
        for (int mt = 0; mt < 2; mt++) {
            #pragma unroll
            for (int rs = 0; rs < 2; rs++) {
                const int row = wm * 32 + mt * 16 + gid + 8 * rs;
                float4 cc = cv[mt][rs];
                float cin[4] = {cc.x, cc.y, cc.z, cc.w};
                float hv[4], cw[4];
                #pragma unroll
                for (int b = 0; b < 2; b++)
                    #pragma unroll
                    for (int e = 0; e < 2; e++) {
                        const int s = 2 * b + e, ci = rs * 2 + e;
                        float it = fsig(acc[mt][0 + b][ci]);
                        float ft = fsig(acc[mt][2 + b][ci]);
                        float gt = htanh(acc[mt][4 + b][ci]);
                        float ot = fsig(acc[mt][6 + b][ci]);
                        float ct = ft * cin[s] + it * gt;
                        hv[s] = ot * htanh(ct); cw[s] = ct;
                    }
                float4 hq = make_float4(hv[0], hv[1], hv[2], hv[3]);
                float4 cq = make_float4(cw[0], cw[1], cw[2], cw[3]);
                size_t o = (size_t)(rowbase + row) * HDIM + colbase4;
                *(float4*)(out_h + o)  = hq;
                *(float4*)(out_h2 + o) = hq;
                *(float4*)(out_c + o)  = cq;
            }
        }
    }
}

extern "C" void kernel_launch(void* const* d_in, const int* in_sizes, int n_in,
                              void* d_out, int out_size) {
    WP p;
    for (int g = 0; g < 4; g++) {
        p.Wx[g] = (const float*)d_in[3 + 4 * g];
        p.bx[g] = (const float*)d_in[4 + 4 * g];
        p.Wh[g] = (const float*)d_in[5 + 4 * g];
        p.bh[g] = (const float*)d_in[6 + 4 * g];
    }
    prep_kernel<<<(512 * 144 + 255) / 256, 256>>>(p);

    int dev = 0, sms = 0;
    cudaGetDevice(&dev);
    cudaDeviceGetAttribute(&sms, cudaDevAttrMultiProcessorCount, dev);
    if (sms <= 0) sms = 152;
    int grid = sms * 2;   // 2 CTAs per SM, nh pairs co-resident
    cudaFuncSetAttribute(lstm_kernel, cudaFuncAttributeMaxDynamicSharedMemorySize, SMEM_BYTES);
    lstm_kernel<<<grid, NTHREADS, SMEM_BYTES>>>(
        (const float*)d_in[0], (const float*)d_in[1], (const float*)d_in[2], (float*)d_out);
}